// round 8
// baseline (speedup 1.0000x reference)
#include <cuda_runtime.h>
#include <cuda_fp16.h>
#include <cuda_bf16.h>
#include <math.h>
#include <stdint.h>

#define NT 8192
#define NC 8192
#define DIM 128
#define NTOT 16384
#define SCALE_S 16384.0f
#define INV_S   (1.0f / 16384.0f)
#define RPB 16

#define LDS_H 136
#define SMEM_MMA (2 * 128 * LDS_H * 2)   // A + B tiles

// ---------------- device globals ----------------
__device__ __nv_bfloat16 g_XtB[NT * DIM];
__device__ __nv_bfloat16 g_XcB[NC * DIM];
__device__ float  g_normT[NT];
__device__ float  g_normC[NC];
__device__ int    g_it[NT];
__device__ int    g_ic[NC];
__device__ __half g_Mh[(size_t)NT * NC];   // 128 MB distances (fp16)
__device__ __half g_Kh[(size_t)NT * NC];   // 128 MB scaled Gibbs kernel (fp16)
__device__ float  g_u[NT + 1];
__device__ float  g_t[2][NC];
__device__ float  g_sumU_acc;
__device__ double g_sumM;
__device__ int    g_maxbits;
__device__ double g_dval;

struct Scal {
    float eff_lam, kd, delta;
    float sNC, addc;
    float sumS;
    float sumV;
};
__device__ Scal g_sc;

// ---------------- split ----------------
__global__ void split_kernel(const int* __restrict__ hal) {
    __shared__ int wsum[32];
    int t = threadIdx.x;
    int base = t * 16;
    int lab[16];
    int cnt = 0;
#pragma unroll
    for (int k = 0; k < 16; k++) { lab[k] = hal[base + k]; cnt += (lab[k] == 1); }
    int lane = t & 31, wid = t >> 5;
    int inc = cnt;
#pragma unroll
    for (int o = 1; o < 32; o <<= 1) {
        int y = __shfl_up_sync(0xffffffffu, inc, o);
        if (lane >= o) inc += y;
    }
    if (lane == 31) wsum[wid] = inc;
    __syncthreads();
    if (wid == 0) {
        int v = wsum[lane];
#pragma unroll
        for (int o = 1; o < 32; o <<= 1) {
            int y = __shfl_up_sync(0xffffffffu, v, o);
            if (lane >= o) v += y;
        }
        wsum[lane] = v;
    }
    __syncthreads();
    int excl = inc - cnt + (wid > 0 ? wsum[wid - 1] : 0);
    int tpos = excl;
#pragma unroll
    for (int k = 0; k < 16; k++) {
        int i = base + k;
        if (lab[k] == 1) g_it[tpos++] = i;
        else             g_ic[i - tpos] = i;
    }
}

// ---------------- gather (bf16) + norms ----------------
__global__ void gather_kernel(const float* __restrict__ X) {
    int b = blockIdx.x, t = threadIdx.x;
    int src, r;
    if (b < NT) { r = b;      src = g_it[r]; }
    else        { r = b - NT; src = g_ic[r]; }
    float v = X[(size_t)src * DIM + t];
    __nv_bfloat16 bv = __float2bfloat16(v);
    if (b < NT) g_XtB[(size_t)r * DIM + t] = bv;
    else        g_XcB[(size_t)r * DIM + t] = bv;
    float vb = __bfloat162float(bv);
    float sq = vb * vb;
#pragma unroll
    for (int o = 16; o > 0; o >>= 1) sq += __shfl_down_sync(0xffffffffu, sq, o);
    __shared__ float ws[4];
    if ((t & 31) == 0) ws[t >> 5] = sq;
    __syncthreads();
    if (t == 0) {
        float s = ws[0] + ws[1] + ws[2] + ws[3];
        if (b < NT) g_normT[r] = s; else g_normC[r] = s;
    }
}

__global__ void zero_misc_kernel() {
    g_sumM = 0.0;
    g_maxbits = 0;
    g_dval = 0.0;
}

// ---------------- mma.sync GEMM + distances + stats ----------------
__device__ __forceinline__ uint32_t smem_u32(const void* p) {
    uint32_t a;
    asm("{ .reg .u64 t; cvta.to.shared.u64 t, %1; cvt.u32.u64 %0, t; }" : "=r"(a) : "l"(p));
    return a;
}
__device__ __forceinline__ void ldmat4(uint32_t* r, uint32_t addr) {
    asm volatile("ldmatrix.sync.aligned.m8n8.x4.shared.b16 {%0,%1,%2,%3}, [%4];"
                 : "=r"(r[0]), "=r"(r[1]), "=r"(r[2]), "=r"(r[3]) : "r"(addr));
}
__device__ __forceinline__ void mma16816(float* c, const uint32_t* a, const uint32_t* b) {
    asm volatile(
        "mma.sync.aligned.m16n8k16.row.col.f32.bf16.bf16.f32 "
        "{%0,%1,%2,%3}, {%4,%5,%6,%7}, {%8,%9}, {%0,%1,%2,%3};"
        : "+f"(c[0]), "+f"(c[1]), "+f"(c[2]), "+f"(c[3])
        : "r"(a[0]), "r"(a[1]), "r"(a[2]), "r"(a[3]), "r"(b[0]), "r"(b[1]));
}

__global__ __launch_bounds__(256) void mma_dist_kernel() {
    extern __shared__ __nv_bfloat16 smem[];
    __shared__ float nTs[128], nCs[128];
    __shared__ float rs[8];
    __shared__ float rm[8];

    __nv_bfloat16* As = smem;
    __nv_bfloat16* Bs = smem + 128 * LDS_H;
    int tid = threadIdx.x, ln = tid & 31, w = tid >> 5;
    int wm = w >> 2, wn = w & 3;
    int m0 = blockIdx.y * 128, n0 = blockIdx.x * 128;

    if (tid < 128) nTs[tid] = g_normT[m0 + tid];
    else           nCs[tid - 128] = g_normC[n0 + tid - 128];

    const uint4* gA = (const uint4*)g_XtB + (size_t)m0 * 16;
    const uint4* gB = (const uint4*)g_XcB + (size_t)n0 * 16;
#pragma unroll
    for (int it = 0; it < 8; it++) {
        int idx = tid + it * 256;
        int row = idx >> 4, cc = idx & 15;
        *(uint4*)(As + row * LDS_H + cc * 8) = gA[row * 16 + cc];
        *(uint4*)(Bs + row * LDS_H + cc * 8) = gB[row * 16 + cc];
    }
    __syncthreads();

    uint32_t aAddr[4], bAddr[2];
    {
        int arow = wm * 64 + (ln & 15);
        int acol = (ln >> 4) * 8;
#pragma unroll
        for (int mi = 0; mi < 4; mi++)
            aAddr[mi] = smem_u32(As + (arow + mi * 16) * LDS_H + acol);
        int brow = wn * 32 + (ln & 7) + ((ln >> 4) << 3);
        int bcol = ((ln >> 3) & 1) * 8;
#pragma unroll
        for (int nj = 0; nj < 2; nj++)
            bAddr[nj] = smem_u32(Bs + (brow + nj * 16) * LDS_H + bcol);
    }

    float acc[4][4][4];
#pragma unroll
    for (int mi = 0; mi < 4; mi++)
#pragma unroll
        for (int nt = 0; nt < 4; nt++)
#pragma unroll
            for (int q = 0; q < 4; q++) acc[mi][nt][q] = 0.f;

#pragma unroll
    for (int kk = 0; kk < 8; kk++) {
        uint32_t a[4][4], b[2][4];
#pragma unroll
        for (int mi = 0; mi < 4; mi++) ldmat4(a[mi], aAddr[mi] + kk * 32);
#pragma unroll
        for (int nj = 0; nj < 2; nj++) ldmat4(b[nj], bAddr[nj] + kk * 32);
#pragma unroll
        for (int mi = 0; mi < 4; mi++)
#pragma unroll
            for (int nt = 0; nt < 4; nt++)
                mma16816(acc[mi][nt], a[mi], &b[nt >> 1][(nt & 1) * 2]);
    }

    float lsum = 0.f;
    float lmax = 0.f;
    int gid = ln >> 2, qid = ln & 3;
#pragma unroll
    for (int mi = 0; mi < 4; mi++) {
        int r0l = wm * 64 + mi * 16 + gid;
        int r1l = r0l + 8;
        float nT0 = nTs[r0l], nT1 = nTs[r1l];
        size_t base0 = (size_t)(m0 + r0l) * NC + n0;
        size_t base1 = (size_t)(m0 + r1l) * NC + n0;
#pragma unroll
        for (int nt = 0; nt < 4; nt++) {
            int cl = wn * 32 + nt * 8 + qid * 2;
            float nC0 = nCs[cl], nC1 = nCs[cl + 1];
            float sq00 = fmaxf(nT0 + nC0 - 2.0f * acc[mi][nt][0], 1e-10f);
            float sq01 = fmaxf(nT0 + nC1 - 2.0f * acc[mi][nt][1], 1e-10f);
            float sq10 = fmaxf(nT1 + nC0 - 2.0f * acc[mi][nt][2], 1e-10f);
            float sq11 = fmaxf(nT1 + nC1 - 2.0f * acc[mi][nt][3], 1e-10f);
            float d00 = sq00 * __frsqrt_rn(sq00);
            float d01 = sq01 * __frsqrt_rn(sq01);
            float d10 = sq10 * __frsqrt_rn(sq10);
            float d11 = sq11 * __frsqrt_rn(sq11);
            *(__half2*)(g_Mh + base0 + cl) = __floats2half2_rn(d00, d01);
            *(__half2*)(g_Mh + base1 + cl) = __floats2half2_rn(d10, d11);
            lsum += (d00 + d01) + (d10 + d11);
            lmax = fmaxf(lmax, fmaxf(fmaxf(d00, d01), fmaxf(d10, d11)));
        }
    }
#pragma unroll
    for (int o = 16; o > 0; o >>= 1) {
        lsum += __shfl_down_sync(0xffffffffu, lsum, o);
        lmax = fmaxf(lmax, __shfl_down_sync(0xffffffffu, lmax, o));
    }
    if (ln == 0) { rs[w] = lsum; rm[w] = lmax; }
    __syncthreads();
    if (tid == 0) {
        float ts = 0.f; float tm = 0.f;
#pragma unroll
        for (int i = 0; i < 8; i++) { ts += rs[i]; tm = fmaxf(tm, rm[i]); }
        atomicAdd(&g_sumM, (double)ts);
        atomicMax(&g_maxbits, __float_as_int(tm));
    }
}

// ---------------- scalar prep ----------------
__global__ void prep_kernel() {
    float mean = (float)(g_sumM / ((double)NT * (double)NC));
    float lam = 10.0f / mean;
    float delta = __int_as_float(g_maxbits);
    g_sc.eff_lam = lam;
    g_sc.delta = delta;
    g_sc.kd = __expf(-lam * delta) + 1e-6f;
}

// ---------------- init Sinkhorn state ----------------
__global__ void init_sink_kernel() {
    int i = blockIdx.x * 256 + threadIdx.x;      // 8 x 256 = 2048 float4
    ((float4*)g_t[0])[i] = make_float4(0.f, 0.f, 0.f, 0.f);
    if (i == 0) {
        g_sumU_acc = 0.5f;     // sum of uniform u0 main rows
        g_u[NT] = 0.5f;        // slack u0
    }
}

// ---------------- pass0: K = S*exp(-lam M); g_t[0] += K^T u0 (uniform) ----------------
__global__ __launch_bounds__(256) void pass0_kernel() {
    int tid = threadIdx.x;
    int row0 = blockIdx.x * RPB;
    float lam = g_sc.eff_lam;
    float acc[32];
#pragma unroll
    for (int e = 0; e < 32; e++) acc[e] = 0.f;

#pragma unroll 1
    for (int r = 0; r < RPB; r++) {
        const uint4* mp = (const uint4*)(g_Mh + (size_t)(row0 + r) * NC);
        uint4* kp = (uint4*)(g_Kh + (size_t)(row0 + r) * NC);
        uint4 mv[4];
#pragma unroll
        for (int c = 0; c < 4; c++) mv[c] = mp[tid + 256 * c];
#pragma unroll
        for (int c = 0; c < 4; c++) {
            const __half2* mh = (const __half2*)&mv[c];
            uint4 ov;
            __half2* oh = (__half2*)&ov;
#pragma unroll
            for (int q = 0; q < 4; q++) {
                float2 f = __half22float2(mh[q]);
                float kx = __expf(-lam * f.x) * SCALE_S;
                float ky = __expf(-lam * f.y) * SCALE_S;
                oh[q] = __floats2half2_rn(kx, ky);
                acc[c * 8 + 2 * q]     += kx;
                acc[c * 8 + 2 * q + 1] += ky;
            }
            kp[tid + 256 * c] = ov;
        }
    }
    const float u0 = 0.5f / (float)NT;
    float* tw = g_t[0];
#pragma unroll
    for (int c = 0; c < 4; c++)
#pragma unroll
        for (int e = 0; e < 8; e++)
            atomicAdd(&tw[8 * (tid + 256 * c) + e], acc[c * 8 + e] * u0);
}

// ---------------- zs: zero t[wr], compute per-iteration scalars ----------------
__global__ void zs_kernel(int wr) {
    int i = blockIdx.x * 256 + threadIdx.x;
    ((float4*)g_t[wr])[i] = make_float4(0.f, 0.f, 0.f, 0.f);
    if (i == 0) {
        float sumU = g_sumU_acc;
        float uN = g_u[NT];
        float kd = g_sc.kd;
        g_sc.addc = 1e-6f * sumU + kd * uN;
        g_sc.sNC  = 0.5f / (kd * sumU + (1.0f + 1e-6f) * uN);
        g_sumU_acc = 0.f;
    }
}

// ---------------- 256-thread block reduce ----------------
__device__ __forceinline__ float blk_reduce256(float v) {
    __shared__ float r8[8];
    int t = threadIdx.x;
#pragma unroll
    for (int o = 16; o > 0; o >>= 1) v += __shfl_down_sync(0xffffffffu, v, o);
    if ((t & 31) == 0) r8[t >> 5] = v;
    __syncthreads();
    if (t < 8) {
        float s = r8[t];
#pragma unroll
        for (int o = 4; o > 0; o >>= 1) s += __shfl_down_sync(0x000000ffu, s, o);
        if (t == 0) r8[0] = s;
    }
    __syncthreads();
    float out = r8[0];
    __syncthreads();
    return out;
}

// ---------------- fused: s from t[rd]; 16 u rows; t[rd^1] += K^T u ----------------
__global__ __launch_bounds__(256) void fused_kernel(int rd) {
    __shared__ float2 ssq[4][1024];   // 32 KB SoA
    __shared__ float u_s[RPB];
    int tid = threadIdx.x;
    int w = tid >> 5, ln = tid & 31;
    int row0 = blockIdx.x * RPB;

    // stage A: s from t[rd] (redundant per block)
    float addc = g_sc.addc;
    const float binv = 0.5f / (float)NC;
    float ls = 0.f;
    const float4* tp = (const float4*)(g_t[rd]);
#pragma unroll
    for (int j4 = tid; j4 < NC / 4; j4 += 256) {
        float4 tv = tp[j4];
        float4 sv;
        sv.x = __fdividef(binv, tv.x * INV_S + addc);
        sv.y = __fdividef(binv, tv.y * INV_S + addc);
        sv.z = __fdividef(binv, tv.z * INV_S + addc);
        sv.w = __fdividef(binv, tv.w * INV_S + addc);
        int i = j4 >> 1, qb = (j4 & 1) * 2;
        ssq[qb][i]     = make_float2(sv.x, sv.y);
        ssq[qb + 1][i] = make_float2(sv.z, sv.w);
        ls += sv.x + sv.y + sv.z + sv.w;
    }
    float sumS = blk_reduce256(ls);   // syncthreads inside -> ssq visible
    float sNC = g_sc.sNC;
    float kd = g_sc.kd;
    float add = 1e-6f * sumS + kd * sNC;

    // phase 1: 2 rows per warp, shared ssq reads
    int rowA = row0 + w * 2;
    const uint4* kpA = (const uint4*)(g_Kh + (size_t)rowA * NC);
    const uint4* kpB = (const uint4*)(g_Kh + (size_t)(rowA + 1) * NC);
    float accA = 0.f, accB = 0.f;
#pragma unroll 2
    for (int it = ln; it < NC / 8; it += 32) {
        uint4 ka = kpA[it];
        uint4 kb = kpB[it];
        const __half2* ha = (const __half2*)&ka;
        const __half2* hb = (const __half2*)&kb;
#pragma unroll
        for (int q = 0; q < 4; q++) {
            float2 sf = ssq[q][it];
            float2 fa = __half22float2(ha[q]);
            float2 fb = __half22float2(hb[q]);
            accA = fmaf(fa.x, sf.x, accA);
            accA = fmaf(fa.y, sf.y, accA);
            accB = fmaf(fb.x, sf.x, accB);
            accB = fmaf(fb.y, sf.y, accB);
        }
    }
#pragma unroll
    for (int o = 16; o > 0; o >>= 1) {
        accA += __shfl_down_sync(0xffffffffu, accA, o);
        accB += __shfl_down_sync(0xffffffffu, accB, o);
    }
    const float au = 0.5f / (float)NT;
    if (ln == 0) {
        float uA = au / (accA * INV_S + add);
        float uB = au / (accB * INV_S + add);
        u_s[w * 2] = uA;     g_u[rowA] = uA;
        u_s[w * 2 + 1] = uB; g_u[rowA + 1] = uB;
    }
    __syncthreads();
    if (tid == 0) {
        float us = 0.f;
#pragma unroll
        for (int i = 0; i < RPB; i++) us += u_s[i];
        atomicAdd(&g_sumU_acc, us);
        if (blockIdx.x == 0) {
            g_u[NT] = 0.5f / (kd * sumS + (1.0f + 1e-6f) * sNC);
            g_sc.sumS = sumS;
        }
    }
    __syncthreads();

    // phase 2: t[rd^1] += K^T u over 16 rows, uint4 staged loads
    float acc2[32];
#pragma unroll
    for (int e = 0; e < 32; e++) acc2[e] = 0.f;
#pragma unroll 1
    for (int r = 0; r < RPB; r++) {
        const uint4* kr = (const uint4*)(g_Kh + (size_t)(row0 + r) * NC);
        uint4 kv[4];
#pragma unroll
        for (int c = 0; c < 4; c++) kv[c] = kr[tid + 256 * c];
        float ur = u_s[r];
#pragma unroll
        for (int c = 0; c < 4; c++) {
            const __half2* kh = (const __half2*)&kv[c];
#pragma unroll
            for (int q = 0; q < 4; q++) {
                float2 kf = __half22float2(kh[q]);
                acc2[c * 8 + 2 * q]     = fmaf(kf.x, ur, acc2[c * 8 + 2 * q]);
                acc2[c * 8 + 2 * q + 1] = fmaf(kf.y, ur, acc2[c * 8 + 2 * q + 1]);
            }
        }
    }
    float* tw = g_t[rd ^ 1];
#pragma unroll
    for (int c = 0; c < 4; c++)
#pragma unroll
        for (int e = 0; e < 8; e++)
            atomicAdd(&tw[8 * (tid + 256 * c) + e], acc2[c * 8 + e]);
}

// ---------------- final: v from t[0]; dval = sum u_i (K+eps)*M v ----------------
__global__ __launch_bounds__(256) void final_kernel() {
    __shared__ float2 vvq[4][1024];
    __shared__ double red[8];
    int tid = threadIdx.x;
    int w = tid >> 5, ln = tid & 31;
    int row0 = blockIdx.x * 8;

    float sumU = g_sumU_acc;
    float uN = g_u[NT];
    float kd = g_sc.kd;
    float addc = 1e-6f * sumU + kd * uN;
    const float binv = 0.5f / (float)NC;
    float lv = 0.f;
    const float4* tp = (const float4*)(g_t[0]);
#pragma unroll
    for (int j4 = tid; j4 < NC / 4; j4 += 256) {
        float4 tv = tp[j4];
        float4 sv;
        sv.x = __fdividef(binv, tv.x * INV_S + addc);
        sv.y = __fdividef(binv, tv.y * INV_S + addc);
        sv.z = __fdividef(binv, tv.z * INV_S + addc);
        sv.w = __fdividef(binv, tv.w * INV_S + addc);
        int i = j4 >> 1, qb = (j4 & 1) * 2;
        vvq[qb][i]     = make_float2(sv.x, sv.y);
        vvq[qb + 1][i] = make_float2(sv.z, sv.w);
        lv += sv.x + sv.y + sv.z + sv.w;
    }
    float sumV = blk_reduce256(lv);
    if (blockIdx.x == 0 && tid == 0) g_sc.sumV = sumV;

    int row = row0 + w;
    const uint4* kp = (const uint4*)(g_Kh + (size_t)row * NC);
    const uint4* mp = (const uint4*)(g_Mh + (size_t)row * NC);
    float acc = 0.f;
#pragma unroll 2
    for (int it = ln; it < NC / 8; it += 32) {
        uint4 kv = kp[it];
        uint4 mv = mp[it];
        const __half2* kh = (const __half2*)&kv;
        const __half2* mh = (const __half2*)&mv;
#pragma unroll
        for (int q = 0; q < 4; q++) {
            float2 kf = __half22float2(kh[q]);
            float2 mf = __half22float2(mh[q]);
            float2 vf = vvq[q][it];
            acc = fmaf((kf.x * INV_S + 1e-6f) * mf.x, vf.x, acc);
            acc = fmaf((kf.y * INV_S + 1e-6f) * mf.y, vf.y, acc);
        }
    }
#pragma unroll
    for (int o = 16; o > 0; o >>= 1) acc += __shfl_down_sync(0xffffffffu, acc, o);
    if (ln == 0) red[w] = (double)g_u[row] * (double)acc;
    __syncthreads();
    if (tid == 0) {
        double tot = red[0] + red[1] + red[2] + red[3] + red[4] + red[5] + red[6] + red[7];
        atomicAdd(&g_dval, tot);
    }
}

__global__ void write_kernel(float* out) {
    double mainsum = g_dval;
    double delta = (double)g_sc.delta;
    double kd = (double)g_sc.kd;
    double sumU = (double)g_sumU_acc;
    double uN = (double)g_u[NT];
    double sumV = (double)g_sc.sumV;
    double vNC = 0.5 / (kd * sumU + (1.0 + 1e-6) * uN);
    double sc = delta * kd * vNC * sumU;
    double sr = delta * kd * uN * sumV;
    out[0] = (float)(2.0 * (mainsum + sc + sr));
}

// ---------------- launch ----------------
extern "C" void kernel_launch(void* const* d_in, const int* in_sizes, int n_in,
                              void* d_out, int out_size) {
    (void)in_sizes; (void)n_in; (void)out_size;
    const float* X = (const float*)d_in[0];
    const int* hal = (const int*)d_in[1];
    float* out = (float*)d_out;

    cudaFuncSetAttribute(mma_dist_kernel, cudaFuncAttributeMaxDynamicSharedMemorySize, SMEM_MMA);

    split_kernel<<<1, 1024>>>(hal);
    gather_kernel<<<NTOT, 128>>>(X);
    zero_misc_kernel<<<1, 1>>>();
    mma_dist_kernel<<<dim3(64, 64), 256, SMEM_MMA>>>();
    prep_kernel<<<1, 1>>>();
    init_sink_kernel<<<8, 256>>>();

    // pass0: build K + t1 = K^T u0 into g_t[0]
    pass0_kernel<<<NT / RPB, 256>>>();

    for (int k = 1; k <= 10; ++k) {
        zs_kernel<<<8, 256>>>(k & 1);                  // zero write target + scalars
        fused_kernel<<<NT / RPB, 256>>>((k - 1) & 1);  // u_k rows + t_{k+1}
    }

    final_kernel<<<1024, 256>>>();                     // v from t[0], main dval sum
    write_kernel<<<1, 1>>>(out);
}

// round 9
// speedup vs baseline: 1.6594x; 1.6594x over previous
#include <cuda_runtime.h>
#include <cuda_fp16.h>
#include <cuda_bf16.h>
#include <math.h>
#include <stdint.h>

#define NT 8192
#define NC 8192
#define DIM 128
#define NTOT 16384
#define SCALE_S 16384.0f
#define INV_S   (1.0f / 16384.0f)

#define LDS_H 136
#define SMEM_MMA (2 * 128 * LDS_H * 2)   // A + B tiles

// ---------------- device globals ----------------
__device__ __nv_bfloat16 g_XtB[NT * DIM];
__device__ __nv_bfloat16 g_XcB[NC * DIM];
__device__ float  g_normT[NT];
__device__ float  g_normC[NC];
__device__ int    g_it[NT];
__device__ int    g_ic[NC];
__device__ __half g_Mh[(size_t)NT * NC];   // 128 MB distances (fp16)
__device__ __half g_Kh[(size_t)NT * NC];   // 128 MB scaled Gibbs kernel (fp16)
__device__ float  g_u[NT + 1];
__device__ float  g_t[NC];                 // single accumulation buffer
__device__ float  g_s[NC];                 // broadcast s / v vector
__device__ float  g_sumU_acc[2];           // ping-pong u sums
__device__ float  g_sumS_part[8];          // per-zs-block partial sums of s
__device__ double g_sumM;
__device__ int    g_maxbits;
__device__ double g_dval;

struct Scal {
    float eff_lam, kd, delta;
    float sNC;
};
__device__ Scal g_sc;

// ---------------- split ----------------
__global__ void split_kernel(const int* __restrict__ hal) {
    __shared__ int wsum[32];
    int t = threadIdx.x;
    int base = t * 16;
    int lab[16];
    int cnt = 0;
#pragma unroll
    for (int k = 0; k < 16; k++) { lab[k] = hal[base + k]; cnt += (lab[k] == 1); }
    int lane = t & 31, wid = t >> 5;
    int inc = cnt;
#pragma unroll
    for (int o = 1; o < 32; o <<= 1) {
        int y = __shfl_up_sync(0xffffffffu, inc, o);
        if (lane >= o) inc += y;
    }
    if (lane == 31) wsum[wid] = inc;
    __syncthreads();
    if (wid == 0) {
        int v = wsum[lane];
#pragma unroll
        for (int o = 1; o < 32; o <<= 1) {
            int y = __shfl_up_sync(0xffffffffu, v, o);
            if (lane >= o) v += y;
        }
        wsum[lane] = v;
    }
    __syncthreads();
    int excl = inc - cnt + (wid > 0 ? wsum[wid - 1] : 0);
    int tpos = excl;
#pragma unroll
    for (int k = 0; k < 16; k++) {
        int i = base + k;
        if (lab[k] == 1) g_it[tpos++] = i;
        else             g_ic[i - tpos] = i;
    }
}

// ---------------- gather (bf16) + norms ----------------
__global__ void gather_kernel(const float* __restrict__ X) {
    int b = blockIdx.x, t = threadIdx.x;
    int src, r;
    if (b < NT) { r = b;      src = g_it[r]; }
    else        { r = b - NT; src = g_ic[r]; }
    float v = X[(size_t)src * DIM + t];
    __nv_bfloat16 bv = __float2bfloat16(v);
    if (b < NT) g_XtB[(size_t)r * DIM + t] = bv;
    else        g_XcB[(size_t)r * DIM + t] = bv;
    float vb = __bfloat162float(bv);
    float sq = vb * vb;
#pragma unroll
    for (int o = 16; o > 0; o >>= 1) sq += __shfl_down_sync(0xffffffffu, sq, o);
    __shared__ float ws[4];
    if ((t & 31) == 0) ws[t >> 5] = sq;
    __syncthreads();
    if (t == 0) {
        float s = ws[0] + ws[1] + ws[2] + ws[3];
        if (b < NT) g_normT[r] = s; else g_normC[r] = s;
    }
}

__global__ void zero_misc_kernel() {
    g_sumM = 0.0;
    g_maxbits = 0;
    g_dval = 0.0;
}

// ---------------- mma.sync GEMM + distances + stats ----------------
__device__ __forceinline__ uint32_t smem_u32(const void* p) {
    uint32_t a;
    asm("{ .reg .u64 t; cvta.to.shared.u64 t, %1; cvt.u32.u64 %0, t; }" : "=r"(a) : "l"(p));
    return a;
}
__device__ __forceinline__ void ldmat4(uint32_t* r, uint32_t addr) {
    asm volatile("ldmatrix.sync.aligned.m8n8.x4.shared.b16 {%0,%1,%2,%3}, [%4];"
                 : "=r"(r[0]), "=r"(r[1]), "=r"(r[2]), "=r"(r[3]) : "r"(addr));
}
__device__ __forceinline__ void mma16816(float* c, const uint32_t* a, const uint32_t* b) {
    asm volatile(
        "mma.sync.aligned.m16n8k16.row.col.f32.bf16.bf16.f32 "
        "{%0,%1,%2,%3}, {%4,%5,%6,%7}, {%8,%9}, {%0,%1,%2,%3};"
        : "+f"(c[0]), "+f"(c[1]), "+f"(c[2]), "+f"(c[3])
        : "r"(a[0]), "r"(a[1]), "r"(a[2]), "r"(a[3]), "r"(b[0]), "r"(b[1]));
}

__global__ __launch_bounds__(256) void mma_dist_kernel() {
    extern __shared__ __nv_bfloat16 smem[];
    __shared__ float nTs[128], nCs[128];
    __shared__ float rs[8];
    __shared__ float rm[8];

    __nv_bfloat16* As = smem;
    __nv_bfloat16* Bs = smem + 128 * LDS_H;
    int tid = threadIdx.x, ln = tid & 31, w = tid >> 5;
    int wm = w >> 2, wn = w & 3;
    int m0 = blockIdx.y * 128, n0 = blockIdx.x * 128;

    if (tid < 128) nTs[tid] = g_normT[m0 + tid];
    else           nCs[tid - 128] = g_normC[n0 + tid - 128];

    const uint4* gA = (const uint4*)g_XtB + (size_t)m0 * 16;
    const uint4* gB = (const uint4*)g_XcB + (size_t)n0 * 16;
#pragma unroll
    for (int it = 0; it < 8; it++) {
        int idx = tid + it * 256;
        int row = idx >> 4, cc = idx & 15;
        *(uint4*)(As + row * LDS_H + cc * 8) = gA[row * 16 + cc];
        *(uint4*)(Bs + row * LDS_H + cc * 8) = gB[row * 16 + cc];
    }
    __syncthreads();

    uint32_t aAddr[4], bAddr[2];
    {
        int arow = wm * 64 + (ln & 15);
        int acol = (ln >> 4) * 8;
#pragma unroll
        for (int mi = 0; mi < 4; mi++)
            aAddr[mi] = smem_u32(As + (arow + mi * 16) * LDS_H + acol);
        int brow = wn * 32 + (ln & 7) + ((ln >> 4) << 3);
        int bcol = ((ln >> 3) & 1) * 8;
#pragma unroll
        for (int nj = 0; nj < 2; nj++)
            bAddr[nj] = smem_u32(Bs + (brow + nj * 16) * LDS_H + bcol);
    }

    float acc[4][4][4];
#pragma unroll
    for (int mi = 0; mi < 4; mi++)
#pragma unroll
        for (int nt = 0; nt < 4; nt++)
#pragma unroll
            for (int q = 0; q < 4; q++) acc[mi][nt][q] = 0.f;

#pragma unroll
    for (int kk = 0; kk < 8; kk++) {
        uint32_t a[4][4], b[2][4];
#pragma unroll
        for (int mi = 0; mi < 4; mi++) ldmat4(a[mi], aAddr[mi] + kk * 32);
#pragma unroll
        for (int nj = 0; nj < 2; nj++) ldmat4(b[nj], bAddr[nj] + kk * 32);
#pragma unroll
        for (int mi = 0; mi < 4; mi++)
#pragma unroll
            for (int nt = 0; nt < 4; nt++)
                mma16816(acc[mi][nt], a[mi], &b[nt >> 1][(nt & 1) * 2]);
    }

    float lsum = 0.f;
    float lmax = 0.f;
    int gid = ln >> 2, qid = ln & 3;
#pragma unroll
    for (int mi = 0; mi < 4; mi++) {
        int r0l = wm * 64 + mi * 16 + gid;
        int r1l = r0l + 8;
        float nT0 = nTs[r0l], nT1 = nTs[r1l];
        size_t base0 = (size_t)(m0 + r0l) * NC + n0;
        size_t base1 = (size_t)(m0 + r1l) * NC + n0;
#pragma unroll
        for (int nt = 0; nt < 4; nt++) {
            int cl = wn * 32 + nt * 8 + qid * 2;
            float nC0 = nCs[cl], nC1 = nCs[cl + 1];
            float sq00 = fmaxf(nT0 + nC0 - 2.0f * acc[mi][nt][0], 1e-10f);
            float sq01 = fmaxf(nT0 + nC1 - 2.0f * acc[mi][nt][1], 1e-10f);
            float sq10 = fmaxf(nT1 + nC0 - 2.0f * acc[mi][nt][2], 1e-10f);
            float sq11 = fmaxf(nT1 + nC1 - 2.0f * acc[mi][nt][3], 1e-10f);
            float d00 = sq00 * __frsqrt_rn(sq00);
            float d01 = sq01 * __frsqrt_rn(sq01);
            float d10 = sq10 * __frsqrt_rn(sq10);
            float d11 = sq11 * __frsqrt_rn(sq11);
            *(__half2*)(g_Mh + base0 + cl) = __floats2half2_rn(d00, d01);
            *(__half2*)(g_Mh + base1 + cl) = __floats2half2_rn(d10, d11);
            lsum += (d00 + d01) + (d10 + d11);
            lmax = fmaxf(lmax, fmaxf(fmaxf(d00, d01), fmaxf(d10, d11)));
        }
    }
#pragma unroll
    for (int o = 16; o > 0; o >>= 1) {
        lsum += __shfl_down_sync(0xffffffffu, lsum, o);
        lmax = fmaxf(lmax, __shfl_down_sync(0xffffffffu, lmax, o));
    }
    if (ln == 0) { rs[w] = lsum; rm[w] = lmax; }
    __syncthreads();
    if (tid == 0) {
        float ts = 0.f; float tm = 0.f;
#pragma unroll
        for (int i = 0; i < 8; i++) { ts += rs[i]; tm = fmaxf(tm, rm[i]); }
        atomicAdd(&g_sumM, (double)ts);
        atomicMax(&g_maxbits, __float_as_int(tm));
    }
}

// ---------------- scalar prep ----------------
__global__ void prep_kernel() {
    float mean = (float)(g_sumM / ((double)NT * (double)NC));
    float lam = 10.0f / mean;
    float delta = __int_as_float(g_maxbits);
    g_sc.eff_lam = lam;
    g_sc.delta = delta;
    g_sc.kd = __expf(-lam * delta) + 1e-6f;
}

// ---------------- convert: Kh = SCALE * exp(-lam * Mh) ----------------
__global__ __launch_bounds__(512) void convert_kernel() {
    float lam = g_sc.eff_lam;
    size_t idx = (size_t)blockIdx.x * 512 + threadIdx.x;
    uint4 mv = ((const uint4*)g_Mh)[idx];
    const __half2* mh = (const __half2*)&mv;
    uint4 ov;
    __half2* oh = (__half2*)&ov;
#pragma unroll
    for (int q = 0; q < 4; q++) {
        float2 f = __half22float2(mh[q]);
        float kx = __expf(-lam * f.x) * SCALE_S;
        float ky = __expf(-lam * f.y) * SCALE_S;
        oh[q] = __floats2half2_rn(kx, ky);
    }
    ((uint4*)g_Kh)[idx] = ov;
}

// ---------------- init Sinkhorn state ----------------
__global__ void init_sink_kernel() {
    int i = blockIdx.x * 256 + threadIdx.x;      // 8 x 256 = 2048 float4
    ((float4*)g_t)[i] = make_float4(0.f, 0.f, 0.f, 0.f);
    if (i == 0) {
        g_sumU_acc[0] = 0.5f;   // sum of uniform u0 main rows
        g_sumU_acc[1] = 0.f;
        g_u[NT] = 0.5f;         // slack u0
    }
}

// ---------------- zs: s = b/(t+slack) ONCE, zero t, partial sums ----------------
// acc_rd: which sumU buffer holds the just-finished u's sum. Zeroes the other.
__global__ __launch_bounds__(1024) void zs_kernel(int acc_rd) {
    __shared__ float r8[32];
    int tid = threadIdx.x;
    int j = blockIdx.x * 1024 + tid;          // 8 blocks x 1024 = 8192
    float sumU = g_sumU_acc[acc_rd];
    float uN = g_u[NT];
    float kd = g_sc.kd;
    float addc = 1e-6f * sumU + kd * uN;
    float sNC = 0.5f / (kd * sumU + (1.0f + 1e-6f) * uN);
    const float binv = 0.5f / (float)NC;

    float tv = g_t[j];
    float sv = __fdividef(binv, tv * INV_S + addc);
    g_s[j] = sv;
    g_t[j] = 0.f;

    // block reduce sum of sv
    float v = sv;
#pragma unroll
    for (int o = 16; o > 0; o >>= 1) v += __shfl_down_sync(0xffffffffu, v, o);
    if ((tid & 31) == 0) r8[tid >> 5] = v;
    __syncthreads();
    if (tid < 32) {
        float s = r8[tid];
#pragma unroll
        for (int o = 16; o > 0; o >>= 1) s += __shfl_down_sync(0xffffffffu, s, o);
        if (tid == 0) g_sumS_part[blockIdx.x] = s;
    }
    if (j == 0) {
        g_sc.sNC = sNC;
        g_sumU_acc[acc_rd ^ 1] = 0.f;        // accumulator for the next u
    }
}

// ---------------- fused: load s; u rows; t += K^T u ----------------
__global__ __launch_bounds__(256) void fused_kernel(int mode, int wr) {
    __shared__ float2 ssq[4][1024];   // 32 KB SoA
    __shared__ float u_s[8];
    __shared__ float s_add[2];        // [0]=add, [1]=sumS
    int tid = threadIdx.x;
    int w = tid >> 5, ln = tid & 31;
    int row0 = blockIdx.x * 8;

    if (mode) {
        // stage A: load s into SoA smem
        const float4* sp = (const float4*)g_s;
#pragma unroll
        for (int j4 = tid; j4 < NC / 4; j4 += 256) {
            float4 sv = sp[j4];
            int i = j4 >> 1, qb = (j4 & 1) * 2;
            ssq[qb][i]     = make_float2(sv.x, sv.y);
            ssq[qb + 1][i] = make_float2(sv.z, sv.w);
        }
        if (tid == 0) {
            float sumS = 0.f;
#pragma unroll
            for (int p = 0; p < 8; p++) sumS += g_sumS_part[p];
            s_add[1] = sumS;
            s_add[0] = 1e-6f * sumS + g_sc.kd * g_sc.sNC;
        }
        __syncthreads();
        float add = s_add[0];

        // phase 1: one warp per row: u = au / ((K s) scaled)
        int row = row0 + w;
        const uint4* kp = (const uint4*)(g_Kh + (size_t)row * NC);
        float acc = 0.f;
#pragma unroll 4
        for (int it = ln; it < NC / 8; it += 32) {
            uint4 kv = kp[it];
            const __half2* kh = (const __half2*)&kv;
#pragma unroll
            for (int q = 0; q < 4; q++) {
                float2 kf = __half22float2(kh[q]);
                float2 sf = ssq[q][it];
                acc = fmaf(kf.x, sf.x, acc);
                acc = fmaf(kf.y, sf.y, acc);
            }
        }
#pragma unroll
        for (int o = 16; o > 0; o >>= 1) acc += __shfl_down_sync(0xffffffffu, acc, o);
        const float au = 0.5f / (float)NT;
        if (ln == 0) {
            float u = au / (acc * INV_S + add);
            u_s[w] = u;
            g_u[row] = u;
        }
        __syncthreads();
        if (tid == 0) {
            float us = u_s[0] + u_s[1] + u_s[2] + u_s[3] + u_s[4] + u_s[5] + u_s[6] + u_s[7];
            atomicAdd(&g_sumU_acc[wr], us);
            if (blockIdx.x == 0) {
                float sumS = s_add[1];
                g_u[NT] = 0.5f / (g_sc.kd * sumS + (1.0f + 1e-6f) * g_sc.sNC);
            }
        }
        __syncthreads();
    } else {
        if (tid < 8) u_s[tid] = 0.5f / (float)NT;
        __syncthreads();
    }

    // phase 2: t += K^T u over this block's 8 rows (L2-hot)
    float2 acc2[16];
#pragma unroll
    for (int q = 0; q < 16; q++) acc2[q] = make_float2(0.f, 0.f);
#pragma unroll 2
    for (int r = 0; r < 8; r++) {
        const __half2* kr = (const __half2*)(g_Kh + (size_t)(row0 + r) * NC);
        float ur = u_s[r];
#pragma unroll
        for (int q = 0; q < 16; q++) {
            float2 kf = __half22float2(kr[q * 256 + tid]);
            acc2[q].x = fmaf(kf.x, ur, acc2[q].x);
            acc2[q].y = fmaf(kf.y, ur, acc2[q].y);
        }
    }
#pragma unroll
    for (int q = 0; q < 16; q++) {
        int c = 2 * (q * 256 + tid);
        atomicAdd(&g_t[c], acc2[q].x);
        atomicAdd(&g_t[c + 1], acc2[q].y);
    }
}

// ---------------- final: v preloaded in g_s; dval = sum u_i (K+eps)*M v ----------------
__global__ __launch_bounds__(256) void final_kernel() {
    __shared__ float2 vvq[4][1024];
    __shared__ double red[8];
    int tid = threadIdx.x;
    int w = tid >> 5, ln = tid & 31;
    int row0 = blockIdx.x * 8;

    const float4* sp = (const float4*)g_s;
#pragma unroll
    for (int j4 = tid; j4 < NC / 4; j4 += 256) {
        float4 sv = sp[j4];
        int i = j4 >> 1, qb = (j4 & 1) * 2;
        vvq[qb][i]     = make_float2(sv.x, sv.y);
        vvq[qb + 1][i] = make_float2(sv.z, sv.w);
    }
    __syncthreads();

    int row = row0 + w;
    const uint4* kp = (const uint4*)(g_Kh + (size_t)row * NC);
    const uint4* mp = (const uint4*)(g_Mh + (size_t)row * NC);
    float acc = 0.f;
#pragma unroll 2
    for (int it = ln; it < NC / 8; it += 32) {
        uint4 kv = kp[it];
        uint4 mv = mp[it];
        const __half2* kh = (const __half2*)&kv;
        const __half2* mh = (const __half2*)&mv;
#pragma unroll
        for (int q = 0; q < 4; q++) {
            float2 kf = __half22float2(kh[q]);
            float2 mf = __half22float2(mh[q]);
            float2 vf = vvq[q][it];
            acc = fmaf((kf.x * INV_S + 1e-6f) * mf.x, vf.x, acc);
            acc = fmaf((kf.y * INV_S + 1e-6f) * mf.y, vf.y, acc);
        }
    }
#pragma unroll
    for (int o = 16; o > 0; o >>= 1) acc += __shfl_down_sync(0xffffffffu, acc, o);
    if (ln == 0) red[w] = (double)g_u[row] * (double)acc;
    __syncthreads();
    if (tid == 0) {
        double tot = red[0] + red[1] + red[2] + red[3] + red[4] + red[5] + red[6] + red[7];
        atomicAdd(&g_dval, tot);
    }
}

__global__ void write_kernel(float* out) {
    double mainsum = g_dval;
    double delta = (double)g_sc.delta;
    double kd = (double)g_sc.kd;
    double sumU = (double)g_sumU_acc[0];     // fused(10) accumulated into buf 0
    double uN = (double)g_u[NT];
    double sumV = 0.0;
#pragma unroll
    for (int p = 0; p < 8; p++) sumV += (double)g_sumS_part[p];
    double vNC = 0.5 / (kd * sumU + (1.0 + 1e-6) * uN);
    double sc = delta * kd * vNC * sumU;     // slack column
    double sr = delta * kd * uN * sumV;      // slack row
    out[0] = (float)(2.0 * (mainsum + sc + sr));
}

// ---------------- launch ----------------
extern "C" void kernel_launch(void* const* d_in, const int* in_sizes, int n_in,
                              void* d_out, int out_size) {
    (void)in_sizes; (void)n_in; (void)out_size;
    const float* X = (const float*)d_in[0];
    const int* hal = (const int*)d_in[1];
    float* out = (float*)d_out;

    cudaFuncSetAttribute(mma_dist_kernel, cudaFuncAttributeMaxDynamicSharedMemorySize, SMEM_MMA);

    split_kernel<<<1, 1024>>>(hal);
    gather_kernel<<<NTOT, 128>>>(X);
    zero_misc_kernel<<<1, 1>>>();
    mma_dist_kernel<<<dim3(64, 64), 256, SMEM_MMA>>>();
    prep_kernel<<<1, 1>>>();
    convert_kernel<<<16384, 512>>>();
    init_sink_kernel<<<8, 256>>>();

    // t = K^T u0 (uniform u0)
    fused_kernel<<<1024, 256>>>(0, 0);

    for (int k = 1; k <= 10; ++k) {
        zs_kernel<<<8, 1024>>>((k - 1) & 1);         // s_k from t; zero t; scalars
        fused_kernel<<<1024, 256>>>(1, k & 1);       // u_k rows + t_{k+1}
    }

    zs_kernel<<<8, 1024>>>(0);                       // v from final t into g_s
    final_kernel<<<1024, 256>>>();
    write_kernel<<<1, 1>>>(out);
}